// round 3
// baseline (speedup 1.0000x reference)
#include <cuda_runtime.h>
#include <cuda_bf16.h>

// Problem constants
#define BB 4
#define SS 2048
#define DD 1024
#define HH 16
#define DKK 64
#define MM (BB * SS)   // 8192

// Scratch: Q, K, V, attention-out, each [8192, 1024] fp32 (32MB).
__device__ float g_Q [MM * DD];
__device__ float g_K [MM * DD];
__device__ float g_V [MM * DD];
__device__ float g_AO[MM * DD];

// ---------------------------------------------------------------------------
// SGEMM (NT): C[M,N] = A[M,K] * B[N,K]^T   (all row-major fp32)
// Tile 128x128x16, 256 threads, 8x8 per-thread register blocking.
// Shared tiles stored transposed [k][m] with +4 padding (keeps LDS.128
// 16B-aligned, spreads banks across the 4 k-rows each loader thread writes).
// ---------------------------------------------------------------------------
__global__ void __launch_bounds__(256) sgemm_nt(
    const float* __restrict__ A, const float* __restrict__ B,
    float* __restrict__ C, int M, int N, int K)
{
    __shared__ float As[16][132];
    __shared__ float Bs[16][132];

    const int tid = threadIdx.x;
    const int bm = blockIdx.y * 128;
    const int bn = blockIdx.x * 128;
    const int tx = tid & 15;     // n-dir (16)
    const int ty = tid >> 4;     // m-dir (16)

    // Loader mapping: each thread loads 2 float4 from A and 2 from B per tile.
    const int lr = tid >> 2;            // row within 64-row half (0..63)
    const int lk = (tid & 3) << 2;      // k offset (float4 aligned)

    const float* Ap = A + (size_t)(bm + lr) * K + lk;
    const float* Bp = B + (size_t)(bn + lr) * K + lk;

    float acc[8][8];
#pragma unroll
    for (int i = 0; i < 8; i++)
#pragma unroll
        for (int j = 0; j < 8; j++) acc[i][j] = 0.f;

    for (int k0 = 0; k0 < K; k0 += 16) {
        // Issue global loads early (overlap with previous tile's tail).
        float4 a0 = *(const float4*)(Ap + k0);
        float4 a1 = *(const float4*)(Ap + (size_t)64 * K + k0);
        float4 b0 = *(const float4*)(Bp + k0);
        float4 b1 = *(const float4*)(Bp + (size_t)64 * K + k0);

        __syncthreads();   // previous iteration's smem reads done
        {
            const float* pa0 = (const float*)&a0;
            const float* pa1 = (const float*)&a1;
            const float* pb0 = (const float*)&b0;
            const float* pb1 = (const float*)&b1;
#pragma unroll
            for (int t = 0; t < 4; t++) {
                As[lk + t][lr]      = pa0[t];
                As[lk + t][64 + lr] = pa1[t];
                Bs[lk + t][lr]      = pb0[t];
                Bs[lk + t][64 + lr] = pb1[t];
            }
        }
        __syncthreads();

#pragma unroll
        for (int k = 0; k < 16; k++) {
            float ar[8], br[8];
            float4 av0 = *(const float4*)&As[k][ty * 4];
            float4 av1 = *(const float4*)&As[k][64 + ty * 4];
            float4 bv0 = *(const float4*)&Bs[k][tx * 4];
            float4 bv1 = *(const float4*)&Bs[k][64 + tx * 4];
            ar[0] = av0.x; ar[1] = av0.y; ar[2] = av0.z; ar[3] = av0.w;
            ar[4] = av1.x; ar[5] = av1.y; ar[6] = av1.z; ar[7] = av1.w;
            br[0] = bv0.x; br[1] = bv0.y; br[2] = bv0.z; br[3] = bv0.w;
            br[4] = bv1.x; br[5] = bv1.y; br[6] = bv1.z; br[7] = bv1.w;
#pragma unroll
            for (int i = 0; i < 8; i++)
#pragma unroll
                for (int j = 0; j < 8; j++)
                    acc[i][j] += ar[i] * br[j];
        }
    }

    // Writeback: rows {bm + ig*64 + ty*4 + i}, cols {bn + jg*64 + tx*4 ..+3}
#pragma unroll
    for (int ig = 0; ig < 2; ig++) {
#pragma unroll
        for (int i = 0; i < 4; i++) {
            int row = bm + ig * 64 + ty * 4 + i;
            float* crow = C + (size_t)row * N + bn;
#pragma unroll
            for (int jg = 0; jg < 2; jg++) {
                float4 v;
                v.x = acc[ig * 4 + i][jg * 4 + 0];
                v.y = acc[ig * 4 + i][jg * 4 + 1];
                v.z = acc[ig * 4 + i][jg * 4 + 2];
                v.w = acc[ig * 4 + i][jg * 4 + 3];
                *(float4*)(crow + jg * 64 + tx * 4) = v;
            }
        }
    }
}

// ---------------------------------------------------------------------------
// Flash attention, fp32. One thread owns one q row (all 64 dims in regs).
// Block = 128 q rows of one (b,h); loop over KV in 32-row tiles with
// online softmax. K/V tile reads are warp-uniform -> smem broadcast.
// Q,K,V,O layouts are [B*S, D] with head h at columns h*64..h*64+63.
// ---------------------------------------------------------------------------
__global__ void __launch_bounds__(128, 2) fa_kernel(
    const float* __restrict__ Q, const float* __restrict__ K,
    const float* __restrict__ V, float* __restrict__ O)
{
    __shared__ float Ks[32][64];
    __shared__ float Vs[32][64];

    const int b = blockIdx.y >> 4;
    const int h = blockIdx.y & 15;
    const int qrow = blockIdx.x * 128 + threadIdx.x;
    const size_t base_bh = (size_t)b * SS * DD + (size_t)h * DKK;

    // Load q row, pre-scaled by 1/sqrt(DK) = 0.125
    float q[64];
    {
        const float* qp = Q + base_bh + (size_t)qrow * DD;
#pragma unroll
        for (int d = 0; d < 64; d += 4) {
            float4 t = *(const float4*)(qp + d);
            q[d + 0] = t.x * 0.125f;
            q[d + 1] = t.y * 0.125f;
            q[d + 2] = t.z * 0.125f;
            q[d + 3] = t.w * 0.125f;
        }
    }

    float acc[64];
#pragma unroll
    for (int d = 0; d < 64; d++) acc[d] = 0.f;
    float m = -1e30f;
    float l = 0.f;

    for (int kv0 = 0; kv0 < SS; kv0 += 32) {
        __syncthreads();   // previous tile's smem reads done
#pragma unroll
        for (int p = 0; p < 4; p++) {
            int i = threadIdx.x + p * 128;    // float4 index 0..511
            int r = i >> 4;
            int c = (i & 15) << 2;
            const float* ksrc = K + base_bh + (size_t)(kv0 + r) * DD + c;
            const float* vsrc = V + base_bh + (size_t)(kv0 + r) * DD + c;
            *(float4*)&Ks[r][c] = *(const float4*)ksrc;
            *(float4*)&Vs[r][c] = *(const float4*)vsrc;
        }
        __syncthreads();

        // scores for this tile
        float s[32];
#pragma unroll
        for (int j = 0; j < 32; j++) {
            float sj = 0.f;
#pragma unroll
            for (int d = 0; d < 64; d += 4) {
                float4 kv = *(const float4*)&Ks[j][d];
                sj += q[d + 0] * kv.x;
                sj += q[d + 1] * kv.y;
                sj += q[d + 2] * kv.z;
                sj += q[d + 3] * kv.w;
            }
            s[j] = sj;
        }

        // online softmax update
        float mt = m;
#pragma unroll
        for (int j = 0; j < 32; j++) mt = fmaxf(mt, s[j]);
        float corr = __expf(m - mt);
        m = mt;
        l *= corr;
#pragma unroll
        for (int d = 0; d < 64; d++) acc[d] *= corr;

#pragma unroll
        for (int j = 0; j < 32; j++) {
            float p = __expf(s[j] - m);
            l += p;
#pragma unroll
            for (int d = 0; d < 64; d += 4) {
                float4 vv = *(const float4*)&Vs[j][d];
                acc[d + 0] += p * vv.x;
                acc[d + 1] += p * vv.y;
                acc[d + 2] += p * vv.z;
                acc[d + 3] += p * vv.w;
            }
        }
    }

    const float inv = 1.f / l;
    float* op = O + base_bh + (size_t)qrow * DD;
#pragma unroll
    for (int d = 0; d < 64; d += 4) {
        float4 t;
        t.x = acc[d + 0] * inv;
        t.y = acc[d + 1] * inv;
        t.z = acc[d + 2] * inv;
        t.w = acc[d + 3] * inv;
        *(float4*)(op + d) = t;
    }
}

// ---------------------------------------------------------------------------
extern "C" void kernel_launch(void* const* d_in, const int* in_sizes, int n_in,
                              void* d_out, int out_size)
{
    const float* X  = (const float*)d_in[0];
    const float* Wq = (const float*)d_in[1];
    const float* Wk = (const float*)d_in[2];
    const float* Wv = (const float*)d_in[3];
    const float* Wo = (const float*)d_in[4];
    float* out = (float*)d_out;

    float *Qb, *Kb, *Vb, *AOb;
    cudaGetSymbolAddress((void**)&Qb,  g_Q);
    cudaGetSymbolAddress((void**)&Kb,  g_K);
    cudaGetSymbolAddress((void**)&Vb,  g_V);
    cudaGetSymbolAddress((void**)&AOb, g_AO);

    dim3 gemm_grid(DD / 128, MM / 128);   // (8, 64)
    dim3 gemm_block(256);

    sgemm_nt<<<gemm_grid, gemm_block>>>(X, Wq, Qb, MM, DD, DD);
    sgemm_nt<<<gemm_grid, gemm_block>>>(X, Wk, Kb, MM, DD, DD);
    sgemm_nt<<<gemm_grid, gemm_block>>>(X, Wv, Vb, MM, DD, DD);

    dim3 fa_grid(SS / 128, BB * HH);      // (16, 64)
    fa_kernel<<<fa_grid, 128>>>(Qb, Kb, Vb, AOb);

    sgemm_nt<<<gemm_grid, gemm_block>>>(AOb, Wo, out, MM, DD, DD);
}

// round 4
// speedup vs baseline: 1.0010x; 1.0010x over previous
#include <cuda_runtime.h>
#include <cuda_bf16.h>

// Problem constants
#define BB 4
#define SS 2048
#define DD 1024
#define HH 16
#define DKK 64
#define MM (BB * SS)   // 8192

// Scratch: Q, K, V, attention-out, each [8192, 1024] fp32 (32MB).
__device__ float g_Q [MM * DD];
__device__ float g_K [MM * DD];
__device__ float g_V [MM * DD];
__device__ float g_AO[MM * DD];

// ---------------------------------------------------------------------------
// SGEMM (NT): C[M,N] = A[M,K] * B[N,K]^T   (all row-major fp32)
// Tile 128x128x16, 256 threads, 8x8 per-thread register blocking.
// Shared tiles stored transposed [k][m] with +4 padding (keeps LDS.128
// 16B-aligned, spreads banks across the 4 k-rows each loader thread writes).
// ---------------------------------------------------------------------------
__global__ void __launch_bounds__(256) sgemm_nt(
    const float* __restrict__ A, const float* __restrict__ B,
    float* __restrict__ C, int M, int N, int K)
{
    __shared__ float As[16][132];
    __shared__ float Bs[16][132];

    const int tid = threadIdx.x;
    const int bm = blockIdx.y * 128;
    const int bn = blockIdx.x * 128;
    const int tx = tid & 15;     // n-dir (16)
    const int ty = tid >> 4;     // m-dir (16)

    // Loader mapping: each thread loads 2 float4 from A and 2 from B per tile.
    const int lr = tid >> 2;            // row within 64-row half (0..63)
    const int lk = (tid & 3) << 2;      // k offset (float4 aligned)

    const float* Ap = A + (size_t)(bm + lr) * K + lk;
    const float* Bp = B + (size_t)(bn + lr) * K + lk;

    float acc[8][8];
#pragma unroll
    for (int i = 0; i < 8; i++)
#pragma unroll
        for (int j = 0; j < 8; j++) acc[i][j] = 0.f;

    for (int k0 = 0; k0 < K; k0 += 16) {
        // Issue global loads early (overlap with previous tile's tail).
        float4 a0 = *(const float4*)(Ap + k0);
        float4 a1 = *(const float4*)(Ap + (size_t)64 * K + k0);
        float4 b0 = *(const float4*)(Bp + k0);
        float4 b1 = *(const float4*)(Bp + (size_t)64 * K + k0);

        __syncthreads();   // previous iteration's smem reads done
        {
            const float* pa0 = (const float*)&a0;
            const float* pa1 = (const float*)&a1;
            const float* pb0 = (const float*)&b0;
            const float* pb1 = (const float*)&b1;
#pragma unroll
            for (int t = 0; t < 4; t++) {
                As[lk + t][lr]      = pa0[t];
                As[lk + t][64 + lr] = pa1[t];
                Bs[lk + t][lr]      = pb0[t];
                Bs[lk + t][64 + lr] = pb1[t];
            }
        }
        __syncthreads();

#pragma unroll
        for (int k = 0; k < 16; k++) {
            float ar[8], br[8];
            float4 av0 = *(const float4*)&As[k][ty * 4];
            float4 av1 = *(const float4*)&As[k][64 + ty * 4];
            float4 bv0 = *(const float4*)&Bs[k][tx * 4];
            float4 bv1 = *(const float4*)&Bs[k][64 + tx * 4];
            ar[0] = av0.x; ar[1] = av0.y; ar[2] = av0.z; ar[3] = av0.w;
            ar[4] = av1.x; ar[5] = av1.y; ar[6] = av1.z; ar[7] = av1.w;
            br[0] = bv0.x; br[1] = bv0.y; br[2] = bv0.z; br[3] = bv0.w;
            br[4] = bv1.x; br[5] = bv1.y; br[6] = bv1.z; br[7] = bv1.w;
#pragma unroll
            for (int i = 0; i < 8; i++)
#pragma unroll
                for (int j = 0; j < 8; j++)
                    acc[i][j] += ar[i] * br[j];
        }
    }

    // Writeback: rows {bm + ig*64 + ty*4 + i}, cols {bn + jg*64 + tx*4 ..+3}
#pragma unroll
    for (int ig = 0; ig < 2; ig++) {
#pragma unroll
        for (int i = 0; i < 4; i++) {
            int row = bm + ig * 64 + ty * 4 + i;
            float* crow = C + (size_t)row * N + bn;
#pragma unroll
            for (int jg = 0; jg < 2; jg++) {
                float4 v;
                v.x = acc[ig * 4 + i][jg * 4 + 0];
                v.y = acc[ig * 4 + i][jg * 4 + 1];
                v.z = acc[ig * 4 + i][jg * 4 + 2];
                v.w = acc[ig * 4 + i][jg * 4 + 3];
                *(float4*)(crow + jg * 64 + tx * 4) = v;
            }
        }
    }
}

// ---------------------------------------------------------------------------
// Flash attention, fp32. One thread owns one q row (all 64 dims in regs).
// Block = 128 q rows of one (b,h); loop over KV in 32-row tiles with
// online softmax. K/V tile reads are warp-uniform -> smem broadcast.
// Q,K,V,O layouts are [B*S, D] with head h at columns h*64..h*64+63.
// ---------------------------------------------------------------------------
__global__ void __launch_bounds__(128, 2) fa_kernel(
    const float* __restrict__ Q, const float* __restrict__ K,
    const float* __restrict__ V, float* __restrict__ O)
{
    __shared__ float Ks[32][64];
    __shared__ float Vs[32][64];

    const int b = blockIdx.y >> 4;
    const int h = blockIdx.y & 15;
    const int qrow = blockIdx.x * 128 + threadIdx.x;
    const size_t base_bh = (size_t)b * SS * DD + (size_t)h * DKK;

    // Load q row, pre-scaled by 1/sqrt(DK) = 0.125
    float q[64];
    {
        const float* qp = Q + base_bh + (size_t)qrow * DD;
#pragma unroll
        for (int d = 0; d < 64; d += 4) {
            float4 t = *(const float4*)(qp + d);
            q[d + 0] = t.x * 0.125f;
            q[d + 1] = t.y * 0.125f;
            q[d + 2] = t.z * 0.125f;
            q[d + 3] = t.w * 0.125f;
        }
    }

    float acc[64];
#pragma unroll
    for (int d = 0; d < 64; d++) acc[d] = 0.f;
    float m = -1e30f;
    float l = 0.f;

    for (int kv0 = 0; kv0 < SS; kv0 += 32) {
        __syncthreads();   // previous tile's smem reads done
#pragma unroll
        for (int p = 0; p < 4; p++) {
            int i = threadIdx.x + p * 128;    // float4 index 0..511
            int r = i >> 4;
            int c = (i & 15) << 2;
            const float* ksrc = K + base_bh + (size_t)(kv0 + r) * DD + c;
            const float* vsrc = V + base_bh + (size_t)(kv0 + r) * DD + c;
            *(float4*)&Ks[r][c] = *(const float4*)ksrc;
            *(float4*)&Vs[r][c] = *(const float4*)vsrc;
        }
        __syncthreads();

        // scores for this tile
        float s[32];
#pragma unroll
        for (int j = 0; j < 32; j++) {
            float sj = 0.f;
#pragma unroll
            for (int d = 0; d < 64; d += 4) {
                float4 kv = *(const float4*)&Ks[j][d];
                sj += q[d + 0] * kv.x;
                sj += q[d + 1] * kv.y;
                sj += q[d + 2] * kv.z;
                sj += q[d + 3] * kv.w;
            }
            s[j] = sj;
        }

        // online softmax update
        float mt = m;
#pragma unroll
        for (int j = 0; j < 32; j++) mt = fmaxf(mt, s[j]);
        float corr = __expf(m - mt);
        m = mt;
        l *= corr;
#pragma unroll
        for (int d = 0; d < 64; d++) acc[d] *= corr;

#pragma unroll
        for (int j = 0; j < 32; j++) {
            float p = __expf(s[j] - m);
            l += p;
#pragma unroll
            for (int d = 0; d < 64; d += 4) {
                float4 vv = *(const float4*)&Vs[j][d];
                acc[d + 0] += p * vv.x;
                acc[d + 1] += p * vv.y;
                acc[d + 2] += p * vv.z;
                acc[d + 3] += p * vv.w;
            }
        }
    }

    const float inv = 1.f / l;
    float* op = O + base_bh + (size_t)qrow * DD;
#pragma unroll
    for (int d = 0; d < 64; d += 4) {
        float4 t;
        t.x = acc[d + 0] * inv;
        t.y = acc[d + 1] * inv;
        t.z = acc[d + 2] * inv;
        t.w = acc[d + 3] * inv;
        *(float4*)(op + d) = t;
    }
}

// ---------------------------------------------------------------------------
extern "C" void kernel_launch(void* const* d_in, const int* in_sizes, int n_in,
                              void* d_out, int out_size)
{
    const float* X  = (const float*)d_in[0];
    const float* Wq = (const float*)d_in[1];
    const float* Wk = (const float*)d_in[2];
    const float* Wv = (const float*)d_in[3];
    const float* Wo = (const float*)d_in[4];
    float* out = (float*)d_out;

    float *Qb, *Kb, *Vb, *AOb;
    cudaGetSymbolAddress((void**)&Qb,  g_Q);
    cudaGetSymbolAddress((void**)&Kb,  g_K);
    cudaGetSymbolAddress((void**)&Vb,  g_V);
    cudaGetSymbolAddress((void**)&AOb, g_AO);

    dim3 gemm_grid(DD / 128, MM / 128);   // (8, 64)
    dim3 gemm_block(256);

    sgemm_nt<<<gemm_grid, gemm_block>>>(X, Wq, Qb, MM, DD, DD);
    sgemm_nt<<<gemm_grid, gemm_block>>>(X, Wk, Kb, MM, DD, DD);
    sgemm_nt<<<gemm_grid, gemm_block>>>(X, Wv, Vb, MM, DD, DD);

    dim3 fa_grid(SS / 128, BB * HH);      // (16, 64)
    fa_kernel<<<fa_grid, 128>>>(Qb, Kb, Vb, AOb);

    sgemm_nt<<<gemm_grid, gemm_block>>>(AOb, Wo, out, MM, DD, DD);
}